// round 16
// baseline (speedup 1.0000x reference)
#include <cuda_runtime.h>
#include <cuda_bf16.h>
#include <cstdint>

#define NGG 6
#define NN 6000
#define EE 96000
#define CC 128
#define NPAIR 21
#define NROWP 6016   // NN padded to multiple of 128
#define NBLK 47      // row tiles of 128 (fused + gmp)

// ---------------- device scratch ----------------
__device__ float g_deg4[(size_t)NGG * NN * 4];    // weighted degree per layer (raw)
__device__ int   g_cntn[NGG * NN];                // in-edge count per node
__device__ int   g_off[NGG * NN];                 // CSR start offsets
__device__ int   g_cur[NGG * NN];                 // fill cursors
__device__ int   g_csr[NGG * EE];                 // source node per CSR slot
__device__ float g_enorm[(size_t)NGG * EE * 4];   // per-edge per-layer norm coeff
__device__ __nv_bfloat16 g_xb[(size_t)NGG * NN * CC];     // x in bf16 (gather src)
__device__ __nv_bfloat16 g_Zb[(size_t)NGG * 4 * NN * CC]; // gathered x, bf16
__device__ float g_gmp[NGG * NBLK * CC];          // g_matrix per-block partials
__device__ __nv_bfloat16 g_xnb[(size_t)NGG * NROWP * CC]; // normalized rows, bf16
__device__ __nv_bfloat16 g_Wh[2 * 4 * 4 * 4096];  // weights hi (transposed chunks)
__device__ __nv_bfloat16 g_Wl[2 * 4 * 4 * 4096];  // weights lo
__device__ unsigned int g_cnt[NPAIR];

__constant__ int cP1[NPAIR] = {0,0,0,0,0,0, 1,1,1,1,1, 2,2,2,2, 3,3,3, 4,4, 5};
__constant__ int cP2[NPAIR] = {0,1,2,3,4,5, 1,2,3,4,5, 2,3,4,5, 3,4,5, 4,5, 5};

// s-space bin boundaries: bnd[k] = atanh(k/10.5 - 1), k=1..20; sentinels at ends
__constant__ float c_bnd[22] = {
    -3e38f,
    -1.49786614f, -1.12564590f, -0.89587974f, -0.72345949f, -0.58157540f,
    -0.45814537f, -0.34657359f, -0.24275391f, -0.14384104f, -0.04765509f,
     0.04765509f,  0.14384104f,  0.24275391f,  0.34657359f,  0.45814537f,
     0.58157540f,  0.72345949f,  0.89587974f,  1.12564590f,  1.49786614f,
     3e38f };

__device__ __forceinline__ uint32_t smem_u32(const void* p) {
    uint32_t a;
    asm("{ .reg .u64 t; cvta.to.shared.u64 t, %1; cvt.u32.u64 %0, t; }"
        : "=r"(a) : "l"(p));
    return a;
}
#define SWZ128(off) ((off) ^ (((off) >> 3) & 0x70))

__device__ __forceinline__ uint32_t pk_bf16(float a, float b) {
    __nv_bfloat162 t = __floats2bfloat162_rn(a, b);
    return *(uint32_t*)&t;
}
#define LDSM4(r0, r1, r2, r3, addr) \
    asm volatile("ldmatrix.sync.aligned.m8n8.x4.shared.b16 {%0,%1,%2,%3}, [%4];" \
        : "=r"(r0), "=r"(r1), "=r"(r2), "=r"(r3) : "r"(addr))
#define MMA_BF16(acc, a, b0, b1) \
    asm volatile("mma.sync.aligned.m16n8k16.row.col.f32.bf16.bf16.f32 " \
        "{%0,%1,%2,%3}, {%4,%5,%6,%7}, {%8,%9}, {%0,%1,%2,%3};" \
        : "+f"((acc)[0]), "+f"((acc)[1]), "+f"((acc)[2]), "+f"((acc)[3]) \
        : "r"((a)[0]), "r"((a)[1]), "r"((a)[2]), "r"((a)[3]), "r"(b0), "r"(b1))

// ---------------- setup + weight hi/lo split + x -> bf16 ----------------
__global__ void k_setup(const float* __restrict__ x,
                        const float* __restrict__ gW, const float* __restrict__ Wsm) {
    int i = blockIdx.x * blockDim.x + threadIdx.x;
    if (i < NGG * NN * CC / 2) {                // convert x pairs -> bf16
        float2 v = ((const float2*)x)[i];
        ((uint32_t*)g_xb)[i] = pk_bf16(v.x, v.y);
    }
    if (i < NGG * NN * 4) g_deg4[i] = 1.0f;     // self-loop weight
    if (i < NGG * NN) g_cntn[i] = 0;
    if (i < NPAIR) g_cnt[i] = 0u;
    if (i < NGG * 16 * CC) {                    // zero 16 pad rows
        int g = i / (16 * CC), rem = i - g * (16 * CC);
        g_xnb[((size_t)g * NROWP + NN) * CC + rem] = __float2bfloat16(0.f);
    }
    if (i < 2 * 4 * 4 * 4096) {
        // index i = ((mat*4 + layer)*4 + chunk)*4096 + n*32 + k ; source [layer][k][n]
        int mat = i >> 16;
        int layer = (i >> 14) & 3;
        int chunk = (i >> 12) & 3;
        int n = (i >> 5) & 127;
        int k = i & 31;
        const float* src = mat ? Wsm : gW;
        float wv = src[((size_t)layer * 128 + chunk * 32 + k) * 128 + n];
        __nv_bfloat16 hb = __float2bfloat16(wv);
        float lres = wv - __bfloat162float(hb);
        g_Wh[i] = hb;
        g_Wl[i] = __float2bfloat16(lres);
    }
}

// ---------------- per-node in-degree count + weighted degree ----------------
__global__ void k_deg(const int* __restrict__ ei, const float* __restrict__ ea) {
    int i = blockIdx.x * blockDim.x + threadIdx.x;
    if (i >= NGG * EE) return;
    int g = i / EE, e = i - g * EE;
    int c = ei[(size_t)g * 2 * EE + EE + e];
    const float* w = ea + ((size_t)g * EE + e) * 6;
    float2 wa = *(const float2*)(w + 2);
    float2 wb = *(const float2*)(w + 4);
    asm volatile("red.global.add.v4.f32 [%0], {%1, %2, %3, %4};"
                 :: "l"(&g_deg4[(size_t)(g * NN + c) * 4]),
                    "f"(wa.x), "f"(wa.y), "f"(wb.x), "f"(wb.y) : "memory");
    atomicAdd(&g_cntn[g * NN + c], 1);
}

// ---------------- CSR offsets ----------------
__global__ void __launch_bounds__(256) k_scan() {
    __shared__ int ps[256];
    int g = blockIdx.x, t = threadIdx.x;
    const int PT = 24;
    int loc[PT];
    int s = 0;
    if (t < 250) {
        int base = g * NN + t * PT;
#pragma unroll
        for (int i = 0; i < PT; i++) { loc[i] = g_cntn[base + i]; s += loc[i]; }
    }
    ps[t] = s;
    __syncthreads();
    for (int o = 1; o < 256; o <<= 1) {
        int v = (t >= o) ? ps[t - o] : 0;
        __syncthreads();
        ps[t] += v;
        __syncthreads();
    }
    if (t < 250) {
        int run = ps[t] - s;
        int base = g * NN + t * PT;
#pragma unroll
        for (int i = 0; i < PT; i++) {
            g_off[base + i] = run;
            g_cur[base + i] = run;
            run += loc[i];
        }
    }
}

// ---------------- CSR fill + per-edge norm coefficients (rsqrt inline) -------
__global__ void k_fill(const int* __restrict__ ei, const float* __restrict__ ea) {
    int i = blockIdx.x * blockDim.x + threadIdx.x;
    if (i >= NGG * EE) return;
    int g = i / EE, e = i - g * EE;
    int r = ei[(size_t)g * 2 * EE + e];
    int c = ei[(size_t)g * 2 * EE + EE + e];
    int pos = atomicAdd(&g_cur[g * NN + c], 1);
    g_csr[g * EE + pos] = r;
    const float* w = ea + ((size_t)g * EE + e) * 6;
    float2 wa = *(const float2*)(w + 2);
    float2 wb = *(const float2*)(w + 4);
    float4 dr = *(const float4*)&g_deg4[(size_t)(g * NN + r) * 4];
    float4 dc = *(const float4*)&g_deg4[(size_t)(g * NN + c) * 4];
    float4 nm;
    nm.x = rsqrtf(dr.x) * wa.x * rsqrtf(dc.x);
    nm.y = rsqrtf(dr.y) * wa.y * rsqrtf(dc.y);
    nm.z = rsqrtf(dr.z) * wb.x * rsqrtf(dc.z);
    nm.w = rsqrtf(dr.w) * wb.y * rsqrtf(dc.w);
    *(float4*)&g_enorm[((size_t)g * EE + pos) * 4] = nm;
}

// ---------------- gather bf16 x:  Z_l[c] = dis_l[c]^2 x[c] + sum_in nrm_l x[r]
__global__ void __launch_bounds__(256) k_gather() {
    int w = (blockIdx.x * 256 + threadIdx.x) >> 5;
    int lane = threadIdx.x & 31;
    if (w >= NGG * NN) return;
    int g = w / NN, c = w - g * NN;
    const uint2* Xg = (const uint2*)(g_xb + (size_t)g * NN * CC);

    uint2 xcu = Xg[(size_t)c * 32 + lane];
    float xc0 = __uint_as_float(xcu.x << 16);
    float xc1 = __uint_as_float(xcu.x & 0xffff0000u);
    float xc2 = __uint_as_float(xcu.y << 16);
    float xc3 = __uint_as_float(xcu.y & 0xffff0000u);
    float4 d4 = *(const float4*)&g_deg4[(size_t)(g * NN + c) * 4];
    float r0 = rsqrtf(d4.x), r1 = rsqrtf(d4.y), r2 = rsqrtf(d4.z), r3 = rsqrtf(d4.w);
    float sc[4] = {r0 * r0, r1 * r1, r2 * r2, r3 * r3};
    float4 acc[4];
#pragma unroll
    for (int l = 0; l < 4; l++)
        acc[l] = make_float4(xc0 * sc[l], xc1 * sc[l], xc2 * sc[l], xc3 * sc[l]);
    int start = g_off[g * NN + c];
    int cnt = g_cntn[g * NN + c];
    const int* csr = g_csr + (size_t)g * EE;
    const float4* en = (const float4*)(g_enorm + (size_t)g * EE * 4);
#pragma unroll 4
    for (int j = 0; j < cnt; j++) {
        int r = __ldg(&csr[start + j]);
        float4 nm = __ldg(&en[start + j]);
        uint2 hu = Xg[(size_t)r * 32 + lane];
        float h0 = __uint_as_float(hu.x << 16);
        float h1 = __uint_as_float(hu.x & 0xffff0000u);
        float h2 = __uint_as_float(hu.y << 16);
        float h3 = __uint_as_float(hu.y & 0xffff0000u);
        acc[0].x += nm.x * h0; acc[0].y += nm.x * h1; acc[0].z += nm.x * h2; acc[0].w += nm.x * h3;
        acc[1].x += nm.y * h0; acc[1].y += nm.y * h1; acc[1].z += nm.y * h2; acc[1].w += nm.y * h3;
        acc[2].x += nm.z * h0; acc[2].y += nm.z * h1; acc[2].z += nm.z * h2; acc[2].w += nm.z * h3;
        acc[3].x += nm.w * h0; acc[3].y += nm.w * h1; acc[3].z += nm.w * h2; acc[3].w += nm.w * h3;
    }
#pragma unroll
    for (int l = 0; l < 4; l++) {
        uint2 pk;
        pk.x = pk_bf16(acc[l].x, acc[l].y);
        pk.y = pk_bf16(acc[l].z, acc[l].w);
        ((uint2*)(g_Zb + ((size_t)(g * 4 + l) * NN + c) * CC))[lane] = pk;
    }
}

// ---------------- fused tensor-core feats + g_matrix + norm ----------------
__global__ void __launch_bounds__(256) k_fused(const float* __restrict__ gb) {
    __shared__ uint8_t smem[36864];
    uint8_t* sZ  = smem;              // 16KB [128 rows][128B] SW128 bf16 (also sO)
    uint8_t* sBh = smem + 16384;      // 10KB [128 n][80B] bf16 hi, K=32 chunk
    uint8_t* sBl = smem + 26624;      // 10KB lo
    __shared__ float sgm[128];
    __shared__ float sns[128];

    int g = blockIdx.y;
    int row0 = blockIdx.x * 128;
    int tid = threadIdx.x;
    int lane = tid & 31, wid = tid >> 5;
    int wm = wid & 3, wn = wid >> 2;
    uint32_t baseZ = smem_u32(sZ), baseBh = smem_u32(sBh), baseBl = smem_u32(sBl);

    float accF[2][8][4];
#pragma unroll
    for (int mt = 0; mt < 2; mt++)
#pragma unroll
        for (int nt = 0; nt < 8; nt++) {
            accF[mt][nt][0]=0.f; accF[mt][nt][1]=0.f; accF[mt][nt][2]=0.f; accF[mt][nt][3]=0.f;
        }

    for (int l = 0; l < 4; l++) {
        float accO[2][8][4];
#pragma unroll
        for (int mt = 0; mt < 2; mt++)
#pragma unroll
            for (int nt = 0; nt < 8; nt++) {
                accO[mt][nt][0]=0.f; accO[mt][nt][1]=0.f; accO[mt][nt][2]=0.f; accO[mt][nt][3]=0.f;
            }
        const uint4* Zb4 = (const uint4*)(g_Zb + (size_t)(g * 4 + l) * NN * CC);

        // ======== GEMM1 ========
        for (int kc64 = 0; kc64 < 2; kc64++) {
            __syncthreads();
#pragma unroll
            for (int it = 0; it < 4; it++) {
                int idx = it * 256 + tid;           // 1024 uint4 slots
                int r = idx >> 3, q = idx & 7;
                uint4 v = make_uint4(0u, 0u, 0u, 0u);
                if (row0 + r < NN) v = Zb4[(size_t)(row0 + r) * 16 + kc64 * 8 + q];
                *(uint4*)(sZ + SWZ128((uint32_t)(r * 128 + q * 16))) = v;
            }
            for (int kc32 = 0; kc32 < 2; kc32++) {
                __syncthreads();
                int chunk = kc64 * 2 + kc32;
                const uint4* srcH = (const uint4*)(g_Wh + (size_t)((0 * 4 + l) * 4 + chunk) * 4096);
                const uint4* srcL = (const uint4*)(g_Wl + (size_t)((0 * 4 + l) * 4 + chunk) * 4096);
#pragma unroll
                for (int it = 0; it < 2; it++) {
                    int idx = it * 256 + tid;       // 512 uint4
                    int n = idx >> 2, q = idx & 3;
                    *(uint4*)(sBh + n * 80 + q * 16) = srcH[idx];
                    *(uint4*)(sBl + n * 80 + q * 16) = srcL[idx];
                }
                __syncthreads();
#pragma unroll
                for (int ks = 0; ks < 2; ks++) {
                    int kin = kc32 * 32 + ks * 16;  // within k64 chunk
                    uint32_t a[2][4];
#pragma unroll
                    for (int mt = 0; mt < 2; mt++) {
                        int r = wm * 32 + mt * 16 + (lane & 15);
                        uint32_t ad = baseZ + SWZ128((uint32_t)(r * 128 + kin * 2 + (lane >> 4) * 16));
                        LDSM4(a[mt][0], a[mt][1], a[mt][2], a[mt][3], ad);
                    }
                    uint32_t bh[4][4], bl[4][4];
#pragma unroll
                    for (int np = 0; np < 4; np++) {
                        int r = wn * 64 + np * 16 + (lane & 7) + ((lane >> 4) << 3);
                        uint32_t off = (uint32_t)(r * 80 + ks * 32 + ((lane >> 3) & 1) * 16);
                        LDSM4(bh[np][0], bh[np][1], bh[np][2], bh[np][3], baseBh + off);
                        LDSM4(bl[np][0], bl[np][1], bl[np][2], bl[np][3], baseBl + off);
                    }
#pragma unroll
                    for (int mt = 0; mt < 2; mt++)
#pragma unroll
                        for (int nt = 0; nt < 8; nt++) {
                            MMA_BF16(accO[mt][nt], a[mt],
                                     bh[nt >> 1][(nt & 1) * 2], bh[nt >> 1][(nt & 1) * 2 + 1]);
                            MMA_BF16(accO[mt][nt], a[mt],
                                     bl[nt >> 1][(nt & 1) * 2], bl[nt >> 1][(nt & 1) * 2 + 1]);
                        }
                }
            }
        }

        // ======== GEMM2 ========
        for (int kc64 = 0; kc64 < 2; kc64++) {
            __syncthreads();                        // prior sZ/sO reads done
            if (wn == kc64) {
                // repack relu(accO + bias) -> sO rows (bf16, SW128)
#pragma unroll
                for (int nt = 0; nt < 8; nt++) {
                    int colb = wn * 64 + nt * 8 + 2 * (lane & 3);
                    float2 bb = *(const float2*)&gb[l * CC + colb];
                    int kloc = nt * 8 + 2 * (lane & 3);
#pragma unroll
                    for (int mt = 0; mt < 2; mt++) {
                        int r = wm * 32 + mt * 16 + (lane >> 2);
                        uint32_t p0 = pk_bf16(fmaxf(accO[mt][nt][0] + bb.x, 0.f),
                                              fmaxf(accO[mt][nt][1] + bb.y, 0.f));
                        uint32_t p1 = pk_bf16(fmaxf(accO[mt][nt][2] + bb.x, 0.f),
                                              fmaxf(accO[mt][nt][3] + bb.y, 0.f));
                        *(uint32_t*)(sZ + SWZ128((uint32_t)(r * 128 + kloc * 2))) = p0;
                        *(uint32_t*)(sZ + SWZ128((uint32_t)((r + 8) * 128 + kloc * 2))) = p1;
                    }
                }
            }
            for (int kc32 = 0; kc32 < 2; kc32++) {
                __syncthreads();
                int chunk = kc64 * 2 + kc32;
                const uint4* srcH = (const uint4*)(g_Wh + (size_t)((1 * 4 + l) * 4 + chunk) * 4096);
                const uint4* srcL = (const uint4*)(g_Wl + (size_t)((1 * 4 + l) * 4 + chunk) * 4096);
#pragma unroll
                for (int it = 0; it < 2; it++) {
                    int idx = it * 256 + tid;
                    int n = idx >> 2, q = idx & 3;
                    *(uint4*)(sBh + n * 80 + q * 16) = srcH[idx];
                    *(uint4*)(sBl + n * 80 + q * 16) = srcL[idx];
                }
                __syncthreads();
#pragma unroll
                for (int ks = 0; ks < 2; ks++) {
                    int kin = kc32 * 32 + ks * 16;
                    uint32_t a[2][4];
#pragma unroll
                    for (int mt = 0; mt < 2; mt++) {
                        int r = wm * 32 + mt * 16 + (lane & 15);
                        uint32_t ad = baseZ + SWZ128((uint32_t)(r * 128 + kin * 2 + (lane >> 4) * 16));
                        LDSM4(a[mt][0], a[mt][1], a[mt][2], a[mt][3], ad);
                    }
                    uint32_t bh[4][4], bl[4][4];
#pragma unroll
                    for (int np = 0; np < 4; np++) {
                        int r = wn * 64 + np * 16 + (lane & 7) + ((lane >> 4) << 3);
                        uint32_t off = (uint32_t)(r * 80 + ks * 32 + ((lane >> 3) & 1) * 16);
                        LDSM4(bh[np][0], bh[np][1], bh[np][2], bh[np][3], baseBh + off);
                        LDSM4(bl[np][0], bl[np][1], bl[np][2], bl[np][3], baseBl + off);
                    }
#pragma unroll
                    for (int mt = 0; mt < 2; mt++)
#pragma unroll
                        for (int nt = 0; nt < 8; nt++) {
                            MMA_BF16(accF[mt][nt], a[mt],
                                     bh[nt >> 1][(nt & 1) * 2], bh[nt >> 1][(nt & 1) * 2 + 1]);
                            MMA_BF16(accF[mt][nt], a[mt],
                                     bl[nt >> 1][(nt & 1) * 2], bl[nt >> 1][(nt & 1) * 2 + 1]);
                        }
                }
            }
        }
    }

    // ======== epilogue: g_matrix partials + row norms + bf16 xn ========
    __syncthreads();
    if (tid < 128) { sgm[tid] = 0.f; sns[tid] = 0.f; }
    __syncthreads();
#pragma unroll
    for (int nt = 0; nt < 8; nt++) {
        float se = 0.f, so = 0.f;
#pragma unroll
        for (int mt = 0; mt < 2; mt++) {
            int r = wm * 32 + mt * 16 + (lane >> 2);
            if (row0 + r < NN)     { se += accF[mt][nt][0]; so += accF[mt][nt][1]; }
            if (row0 + r + 8 < NN) { se += accF[mt][nt][2]; so += accF[mt][nt][3]; }
        }
        int col = wn * 64 + nt * 8 + 2 * (lane & 3);
        atomicAdd(&sgm[col], se);
        atomicAdd(&sgm[col + 1], so);
    }
#pragma unroll
    for (int mt = 0; mt < 2; mt++) {
        float s0 = 0.f, s1 = 0.f;
#pragma unroll
        for (int nt = 0; nt < 8; nt++) {
            s0 += accF[mt][nt][0] * accF[mt][nt][0] + accF[mt][nt][1] * accF[mt][nt][1];
            s1 += accF[mt][nt][2] * accF[mt][nt][2] + accF[mt][nt][3] * accF[mt][nt][3];
        }
        s0 += __shfl_xor_sync(0xffffffffu, s0, 1);
        s0 += __shfl_xor_sync(0xffffffffu, s0, 2);
        s1 += __shfl_xor_sync(0xffffffffu, s1, 1);
        s1 += __shfl_xor_sync(0xffffffffu, s1, 2);
        if ((lane & 3) == 0) {
            int r = wm * 32 + mt * 16 + (lane >> 2);
            atomicAdd(&sns[r], s0);
            atomicAdd(&sns[r + 8], s1);
        }
    }
    __syncthreads();
    if (tid < 32)
        ((float4*)(g_gmp + (size_t)(g * NBLK + blockIdx.x) * CC))[tid] =
            ((const float4*)sgm)[tid];
#pragma unroll
    for (int mt = 0; mt < 2; mt++) {
        int r = wm * 32 + mt * 16 + (lane >> 2);
        float inv0 = 1.0f / fmaxf(sqrtf(sns[r]), 1e-12f);
        float inv1 = 1.0f / fmaxf(sqrtf(sns[r + 8]), 1e-12f);
        bool v0 = (row0 + r < NN), v1 = (row0 + r + 8 < NN);
#pragma unroll
        for (int nt = 0; nt < 8; nt++) {
            int col = wn * 64 + nt * 8 + 2 * (lane & 3);
            if (v0)
                *(uint32_t*)(g_xnb + ((size_t)g * NROWP + row0 + r) * CC + col) =
                    pk_bf16(accF[mt][nt][0] * inv0, accF[mt][nt][1] * inv0);
            if (v1)
                *(uint32_t*)(g_xnb + ((size_t)g * NROWP + row0 + r + 8) * CC + col) =
                    pk_bf16(accF[mt][nt][2] * inv1, accF[mt][nt][3] * inv1);
        }
    }
}

// ---------------- sim: bf16 mma, diag pairs folded for balance ----------------
__global__ void __launch_bounds__(256, 2) k_sim() {
    __shared__ __nv_bfloat16 sA[2][128 * 64];  // two SW128 K=64 chunks (32KB)
    __shared__ __nv_bfloat16 sB[128 * 40];     // K=32 chunk, rows padded to 80B
    __shared__ float s_bnd[22];
    __shared__ unsigned s_part[8];

    int p = blockIdx.y;
    int i1 = cP1[p], i2 = cP2[p];
    int bx = blockIdx.x;
    bool diag = (i1 == i2);
    int rows[2];
    int nrows = 1;
    rows[0] = bx;
    if (diag) {
        if (bx >= 24) return;
        rows[1] = 46 - bx;
        nrows = (bx == 23) ? 1 : 2;
    }

    int tid = threadIdx.x;
    int lane = tid & 31, wid = tid >> 5;
    int wm = wid & 3, wn = wid >> 2;
    if (tid < 22) s_bnd[tid] = c_bnd[tid];

    const __nv_bfloat16* A = g_xnb + (size_t)i1 * NROWP * CC;
    const __nv_bfloat16* B = g_xnb + (size_t)i2 * NROWP * CC;
    uint32_t baseA = smem_u32(sA), baseB = smem_u32(sB);

    unsigned total = 0;
    for (int ri = 0; ri < nrows; ri++) {
        int rb = rows[ri];
        int row0 = rb * 128;
        if (ri) __syncthreads();               // prior row's mma reads of sA done
#pragma unroll
        for (int it = 0; it < 8; it++) {
            int idx = it * 256 + tid;
            int kc = idx >> 10, rem = idx & 1023;
            int r = rem >> 3, q = rem & 7;
            uint32_t sw = (uint32_t)(kc * 16384) + SWZ128((uint32_t)(r * 128 + q * 16));
            *(uint4*)((uint8_t*)sA + sw) =
                *(const uint4*)(A + (size_t)(row0 + r) * CC + kc * 64 + q * 8);
        }
        int byStart = diag ? rb : 0;
        for (int by = byStart; by < 47; by++) {
            unsigned wgt = (diag && by > rb) ? 2u : 1u;
            int col0 = by * 128;
            float acc[2][8][4];
#pragma unroll
            for (int mt = 0; mt < 2; mt++)
#pragma unroll
                for (int nt = 0; nt < 8; nt++) {
                    acc[mt][nt][0] = 0.f; acc[mt][nt][1] = 0.f;
                    acc[mt][nt][2] = 0.f; acc[mt][nt][3] = 0.f;
                }
#pragma unroll
            for (int bc = 0; bc < 4; bc++) {
                __syncthreads();
#pragma unroll
                for (int it = 0; it < 2; it++) {
                    int idx = it * 256 + tid;
                    int r = idx >> 2, q = idx & 3;
                    *(uint4*)((uint8_t*)sB + r * 80 + q * 16) =
                        *(const uint4*)(B + (size_t)(col0 + r) * CC + bc * 32 + q * 8);
                }
                __syncthreads();
#pragma unroll
                for (int ks = 0; ks < 2; ks++) {
                    int kg = bc * 32 + ks * 16;
                    int akc = kg >> 6, akb = (kg & 63) * 2;
                    uint32_t a[2][4];
#pragma unroll
                    for (int mt = 0; mt < 2; mt++) {
                        int r = wm * 32 + mt * 16 + (lane & 15);
                        uint32_t ad = baseA + akc * 16384 +
                            SWZ128((uint32_t)(r * 128 + akb + (lane >> 4) * 16));
                        LDSM4(a[mt][0], a[mt][1], a[mt][2], a[mt][3], ad);
                    }
                    uint32_t b[4][4];
#pragma unroll
                    for (int np = 0; np < 4; np++) {
                        int r = wn * 64 + np * 16 + (lane & 7) + ((lane >> 4) << 3);
                        uint32_t bd = baseB + (uint32_t)(r * 80 + ks * 32 + ((lane >> 3) & 1) * 16);
                        LDSM4(b[np][0], b[np][1], b[np][2], b[np][3], bd);
                    }
#pragma unroll
                    for (int mt = 0; mt < 2; mt++)
#pragma unroll
                        for (int nt = 0; nt < 8; nt++)
                            MMA_BF16(acc[mt][nt], a[mt],
                                     b[nt >> 1][(nt & 1) * 2], b[nt >> 1][(nt & 1) * 2 + 1]);
                }
            }
            // bin accumulators (exact w.r.t. fp32 s; see R8 margin proof)
            int sum = 0;
#pragma unroll
            for (int mt = 0; mt < 2; mt++)
#pragma unroll
                for (int nt = 0; nt < 8; nt++)
#pragma unroll
                    for (int v = 0; v < 4; v++) {
                        float s = acc[mt][nt][v];
                        float t;
                        asm("tanh.approx.f32 %0, %1;" : "=f"(t) : "f"(s));
                        int idx = __float2int_rd(fmaf(t, 10.5f, 10.43f));
                        sum += idx + ((s >= s_bnd[idx + 1]) ? 1 : 0);
                    }
            total += wgt * (unsigned)sum;
        }
    }
#pragma unroll
    for (int o = 16; o; o >>= 1) total += __shfl_xor_sync(0xffffffffu, total, o);
    if (lane == 0) s_part[wid] = total;
    __syncthreads();
    if (tid == 0) {
        unsigned tot = 0;
#pragma unroll
        for (int i = 0; i < 8; i++) tot += s_part[i];
        atomicAdd(&g_cnt[p], tot);
    }
}

// ---------------- finalize: g_matrix reduce + sim values ----------------
__global__ void k_final(float* __restrict__ out) {
    int t = threadIdx.x;
    if (t < NGG * CC) {
        int g = t / CC, c = t - g * CC;
        float s = 0.f;
        for (int b = 0; b < NBLK; b++)
            s += g_gmp[(size_t)(g * NBLK + b) * CC + c];
        out[t] = s / (float)NN;
    }
    if (t < NPAIR) {
        double cnt = (double)g_cnt[t] - 10.0 * 192256.0;
        double v = -1.0 + 0.1 * cnt / ((double)NN * (double)NN);
        out[NGG * CC + cP1[t] * NGG + cP2[t]] = (float)v;
        out[NGG * CC + cP2[t] * NGG + cP1[t]] = (float)v;
    }
}

// ---------------- launch ----------------
extern "C" void kernel_launch(void* const* d_in, const int* in_sizes, int n_in,
                              void* d_out, int out_size) {
    const float* x   = (const float*)d_in[0];
    const int* ei    = (const int*)d_in[1];
    const float* ea  = (const float*)d_in[2];
    const float* gW  = (const float*)d_in[3];
    const float* gb  = (const float*)d_in[4];
    const float* Wsm = (const float*)d_in[5];
    float* out = (float*)d_out;

    k_setup<<<(NGG * NN * CC / 2 + 255) / 256, 256>>>(x, gW, Wsm);
    k_deg<<<(NGG * EE + 255) / 256, 256>>>(ei, ea);
    k_scan<<<NGG, 256>>>();
    k_fill<<<(NGG * EE + 255) / 256, 256>>>(ei, ea);
    k_gather<<<(NGG * NN + 7) / 8, 256>>>();
    k_fused<<<dim3(NBLK, NGG), 256>>>(gb);
    k_sim<<<dim3(47, NPAIR), 256>>>();
    k_final<<<1, 768>>>(out);
}

// round 17
// speedup vs baseline: 1.0053x; 1.0053x over previous
#include <cuda_runtime.h>
#include <cuda_bf16.h>
#include <cstdint>

#define NGG 6
#define NN 6000
#define EE 96000
#define CC 128
#define NPAIR 21
#define NROWP 6016   // NN padded to multiple of 128
#define NBLK 47      // row tiles of 128 (fused + gmp)

// ---------------- device scratch ----------------
__device__ float g_deg4[(size_t)NGG * NN * 4];    // weighted degree per layer (raw)
__device__ int   g_cntn[NGG * NN];                // in-edge count per node
__device__ int   g_off[NGG * NN];                 // CSR start offsets
__device__ int   g_cur[NGG * NN];                 // fill cursors
__device__ int   g_csr[NGG * EE];                 // source node per CSR slot
__device__ float g_enorm[(size_t)NGG * EE * 4];   // per-edge per-layer norm coeff
__device__ __nv_bfloat16 g_Zb[(size_t)NGG * 4 * NN * CC]; // gathered x, bf16
__device__ float g_gmp[NGG * NBLK * CC];          // g_matrix per-block partials
__device__ __nv_bfloat16 g_xnb[(size_t)NGG * NROWP * CC]; // normalized rows, bf16
__device__ __nv_bfloat16 g_Wh[2 * 4 * 4 * 4096];  // weights hi (transposed chunks)
__device__ __nv_bfloat16 g_Wl[2 * 4 * 4 * 4096];  // weights lo
__device__ unsigned int g_cnt[NPAIR];

__constant__ int cP1[NPAIR] = {0,0,0,0,0,0, 1,1,1,1,1, 2,2,2,2, 3,3,3, 4,4, 5};
__constant__ int cP2[NPAIR] = {0,1,2,3,4,5, 1,2,3,4,5, 2,3,4,5, 3,4,5, 4,5, 5};

// s-space bin boundaries: bnd[k] = atanh(k/10.5 - 1), k=1..20; sentinels at ends
__constant__ float c_bnd[22] = {
    -3e38f,
    -1.49786614f, -1.12564590f, -0.89587974f, -0.72345949f, -0.58157540f,
    -0.45814537f, -0.34657359f, -0.24275391f, -0.14384104f, -0.04765509f,
     0.04765509f,  0.14384104f,  0.24275391f,  0.34657359f,  0.45814537f,
     0.58157540f,  0.72345949f,  0.89587974f,  1.12564590f,  1.49786614f,
     3e38f };

__device__ __forceinline__ uint32_t smem_u32(const void* p) {
    uint32_t a;
    asm("{ .reg .u64 t; cvta.to.shared.u64 t, %1; cvt.u32.u64 %0, t; }"
        : "=r"(a) : "l"(p));
    return a;
}
#define SWZ128(off) ((off) ^ (((off) >> 3) & 0x70))

__device__ __forceinline__ uint32_t pk_bf16(float a, float b) {
    __nv_bfloat162 t = __floats2bfloat162_rn(a, b);
    return *(uint32_t*)&t;
}
#define LDSM4(r0, r1, r2, r3, addr) \
    asm volatile("ldmatrix.sync.aligned.m8n8.x4.shared.b16 {%0,%1,%2,%3}, [%4];" \
        : "=r"(r0), "=r"(r1), "=r"(r2), "=r"(r3) : "r"(addr))
#define MMA_BF16(acc, a, b0, b1) \
    asm volatile("mma.sync.aligned.m16n8k16.row.col.f32.bf16.bf16.f32 " \
        "{%0,%1,%2,%3}, {%4,%5,%6,%7}, {%8,%9}, {%0,%1,%2,%3};" \
        : "+f"((acc)[0]), "+f"((acc)[1]), "+f"((acc)[2]), "+f"((acc)[3]) \
        : "r"((a)[0]), "r"((a)[1]), "r"((a)[2]), "r"((a)[3]), "r"(b0), "r"(b1))

// ---------------- setup + one-shot weight hi/lo split ----------------
__global__ void k_setup(const float* __restrict__ gW, const float* __restrict__ Wsm) {
    int i = blockIdx.x * blockDim.x + threadIdx.x;
    if (i < NGG * NN * 4) g_deg4[i] = 1.0f;     // self-loop weight
    if (i < NGG * NN) g_cntn[i] = 0;
    if (i < NPAIR) g_cnt[i] = 0u;
    if (i < NGG * 16 * CC) {                    // zero 16 pad rows
        int g = i / (16 * CC), rem = i - g * (16 * CC);
        g_xnb[((size_t)g * NROWP + NN) * CC + rem] = __float2bfloat16(0.f);
    }
    if (i < 2 * 4 * 4 * 4096) {
        // index i = ((mat*4 + layer)*4 + chunk)*4096 + n*32 + k ; source [layer][k][n]
        int mat = i >> 16;
        int layer = (i >> 14) & 3;
        int chunk = (i >> 12) & 3;
        int n = (i >> 5) & 127;
        int k = i & 31;
        const float* src = mat ? Wsm : gW;
        float wv = src[((size_t)layer * 128 + chunk * 32 + k) * 128 + n];
        __nv_bfloat16 hb = __float2bfloat16(wv);
        float lres = wv - __bfloat162float(hb);
        g_Wh[i] = hb;
        g_Wl[i] = __float2bfloat16(lres);
    }
}

// ---------------- per-node in-degree count + weighted degree ----------------
__global__ void k_deg(const int* __restrict__ ei, const float* __restrict__ ea) {
    int i = blockIdx.x * blockDim.x + threadIdx.x;
    if (i >= NGG * EE) return;
    int g = i / EE, e = i - g * EE;
    int c = ei[(size_t)g * 2 * EE + EE + e];
    const float* w = ea + ((size_t)g * EE + e) * 6;
    float2 wa = *(const float2*)(w + 2);
    float2 wb = *(const float2*)(w + 4);
    asm volatile("red.global.add.v4.f32 [%0], {%1, %2, %3, %4};"
                 :: "l"(&g_deg4[(size_t)(g * NN + c) * 4]),
                    "f"(wa.x), "f"(wa.y), "f"(wb.x), "f"(wb.y) : "memory");
    atomicAdd(&g_cntn[g * NN + c], 1);
}

// ---------------- CSR offsets ----------------
__global__ void __launch_bounds__(256) k_scan() {
    __shared__ int ps[256];
    int g = blockIdx.x, t = threadIdx.x;
    const int PT = 24;
    int loc[PT];
    int s = 0;
    if (t < 250) {
        int base = g * NN + t * PT;
#pragma unroll
        for (int i = 0; i < PT; i++) { loc[i] = g_cntn[base + i]; s += loc[i]; }
    }
    ps[t] = s;
    __syncthreads();
    for (int o = 1; o < 256; o <<= 1) {
        int v = (t >= o) ? ps[t - o] : 0;
        __syncthreads();
        ps[t] += v;
        __syncthreads();
    }
    if (t < 250) {
        int run = ps[t] - s;
        int base = g * NN + t * PT;
#pragma unroll
        for (int i = 0; i < PT; i++) {
            g_off[base + i] = run;
            g_cur[base + i] = run;
            run += loc[i];
        }
    }
}

// ---------------- CSR fill + per-edge norm coefficients (rsqrt inline) -------
__global__ void k_fill(const int* __restrict__ ei, const float* __restrict__ ea) {
    int i = blockIdx.x * blockDim.x + threadIdx.x;
    if (i >= NGG * EE) return;
    int g = i / EE, e = i - g * EE;
    int r = ei[(size_t)g * 2 * EE + e];
    int c = ei[(size_t)g * 2 * EE + EE + e];
    int pos = atomicAdd(&g_cur[g * NN + c], 1);
    g_csr[g * EE + pos] = r;
    const float* w = ea + ((size_t)g * EE + e) * 6;
    float2 wa = *(const float2*)(w + 2);
    float2 wb = *(const float2*)(w + 4);
    float4 dr = *(const float4*)&g_deg4[(size_t)(g * NN + r) * 4];
    float4 dc = *(const float4*)&g_deg4[(size_t)(g * NN + c) * 4];
    float4 nm;
    nm.x = rsqrtf(dr.x) * wa.x * rsqrtf(dc.x);
    nm.y = rsqrtf(dr.y) * wa.y * rsqrtf(dc.y);
    nm.z = rsqrtf(dr.z) * wb.x * rsqrtf(dc.z);
    nm.w = rsqrtf(dr.w) * wb.y * rsqrtf(dc.w);
    *(float4*)&g_enorm[((size_t)g * EE + pos) * 4] = nm;
}

// ---------------- gather fp32 x:  Z_l[c] = dis_l[c]^2 x[c] + sum_in nrm_l x[r]
__global__ void __launch_bounds__(256) k_gather(const float* __restrict__ x) {
    int w = (blockIdx.x * 256 + threadIdx.x) >> 5;
    int lane = threadIdx.x & 31;
    if (w >= NGG * NN) return;
    int g = w / NN, c = w - g * NN;
    const float4* Xg = (const float4*)(x + (size_t)g * NN * CC);

    float4 xc = Xg[(size_t)c * 32 + lane];
    float4 d4 = *(const float4*)&g_deg4[(size_t)(g * NN + c) * 4];
    float r0 = rsqrtf(d4.x), r1 = rsqrtf(d4.y), r2 = rsqrtf(d4.z), r3 = rsqrtf(d4.w);
    float sc[4] = {r0 * r0, r1 * r1, r2 * r2, r3 * r3};
    float4 acc[4];
#pragma unroll
    for (int l = 0; l < 4; l++)
        acc[l] = make_float4(xc.x * sc[l], xc.y * sc[l], xc.z * sc[l], xc.w * sc[l]);
    int start = g_off[g * NN + c];
    int cnt = g_cntn[g * NN + c];
    const int* csr = g_csr + (size_t)g * EE;
    const float4* en = (const float4*)(g_enorm + (size_t)g * EE * 4);
#pragma unroll 4
    for (int j = 0; j < cnt; j++) {
        int r = __ldg(&csr[start + j]);
        float4 nm = __ldg(&en[start + j]);
        float4 h = Xg[(size_t)r * 32 + lane];
        acc[0].x += nm.x * h.x; acc[0].y += nm.x * h.y; acc[0].z += nm.x * h.z; acc[0].w += nm.x * h.w;
        acc[1].x += nm.y * h.x; acc[1].y += nm.y * h.y; acc[1].z += nm.y * h.z; acc[1].w += nm.y * h.w;
        acc[2].x += nm.z * h.x; acc[2].y += nm.z * h.y; acc[2].z += nm.z * h.z; acc[2].w += nm.z * h.w;
        acc[3].x += nm.w * h.x; acc[3].y += nm.w * h.y; acc[3].z += nm.w * h.z; acc[3].w += nm.w * h.w;
    }
#pragma unroll
    for (int l = 0; l < 4; l++) {
        uint2 pk;
        pk.x = pk_bf16(acc[l].x, acc[l].y);
        pk.y = pk_bf16(acc[l].z, acc[l].w);
        ((uint2*)(g_Zb + ((size_t)(g * 4 + l) * NN + c) * CC))[lane] = pk;
    }
}

// ---------------- fused tensor-core feats + g_matrix + norm ----------------
__global__ void __launch_bounds__(256) k_fused(const float* __restrict__ gb) {
    __shared__ uint8_t smem[36864];
    uint8_t* sZ  = smem;              // 16KB [128 rows][128B] SW128 bf16 (also sO)
    uint8_t* sBh = smem + 16384;      // 10KB [128 n][80B] bf16 hi, K=32 chunk
    uint8_t* sBl = smem + 26624;      // 10KB lo
    __shared__ float sgm[128];
    __shared__ float sns[128];

    int g = blockIdx.y;
    int row0 = blockIdx.x * 128;
    int tid = threadIdx.x;
    int lane = tid & 31, wid = tid >> 5;
    int wm = wid & 3, wn = wid >> 2;
    uint32_t baseZ = smem_u32(sZ), baseBh = smem_u32(sBh), baseBl = smem_u32(sBl);

    float accF[2][8][4];
#pragma unroll
    for (int mt = 0; mt < 2; mt++)
#pragma unroll
        for (int nt = 0; nt < 8; nt++) {
            accF[mt][nt][0]=0.f; accF[mt][nt][1]=0.f; accF[mt][nt][2]=0.f; accF[mt][nt][3]=0.f;
        }

    for (int l = 0; l < 4; l++) {
        float accO[2][8][4];
#pragma unroll
        for (int mt = 0; mt < 2; mt++)
#pragma unroll
            for (int nt = 0; nt < 8; nt++) {
                accO[mt][nt][0]=0.f; accO[mt][nt][1]=0.f; accO[mt][nt][2]=0.f; accO[mt][nt][3]=0.f;
            }
        const uint4* Zb4 = (const uint4*)(g_Zb + (size_t)(g * 4 + l) * NN * CC);

        // ======== GEMM1 ========
        for (int kc64 = 0; kc64 < 2; kc64++) {
            __syncthreads();
#pragma unroll
            for (int it = 0; it < 4; it++) {
                int idx = it * 256 + tid;           // 1024 uint4 slots
                int r = idx >> 3, q = idx & 7;
                uint4 v = make_uint4(0u, 0u, 0u, 0u);
                if (row0 + r < NN) v = Zb4[(size_t)(row0 + r) * 16 + kc64 * 8 + q];
                *(uint4*)(sZ + SWZ128((uint32_t)(r * 128 + q * 16))) = v;
            }
            for (int kc32 = 0; kc32 < 2; kc32++) {
                __syncthreads();
                int chunk = kc64 * 2 + kc32;
                const uint4* srcH = (const uint4*)(g_Wh + (size_t)((0 * 4 + l) * 4 + chunk) * 4096);
                const uint4* srcL = (const uint4*)(g_Wl + (size_t)((0 * 4 + l) * 4 + chunk) * 4096);
#pragma unroll
                for (int it = 0; it < 2; it++) {
                    int idx = it * 256 + tid;       // 512 uint4
                    int n = idx >> 2, q = idx & 3;
                    *(uint4*)(sBh + n * 80 + q * 16) = srcH[idx];
                    *(uint4*)(sBl + n * 80 + q * 16) = srcL[idx];
                }
                __syncthreads();
#pragma unroll
                for (int ks = 0; ks < 2; ks++) {
                    int kin = kc32 * 32 + ks * 16;  // within k64 chunk
                    uint32_t a[2][4];
#pragma unroll
                    for (int mt = 0; mt < 2; mt++) {
                        int r = wm * 32 + mt * 16 + (lane & 15);
                        uint32_t ad = baseZ + SWZ128((uint32_t)(r * 128 + kin * 2 + (lane >> 4) * 16));
                        LDSM4(a[mt][0], a[mt][1], a[mt][2], a[mt][3], ad);
                    }
                    uint32_t bh[4][4], bl[4][4];
#pragma unroll
                    for (int np = 0; np < 4; np++) {
                        int r = wn * 64 + np * 16 + (lane & 7) + ((lane >> 4) << 3);
                        uint32_t off = (uint32_t)(r * 80 + ks * 32 + ((lane >> 3) & 1) * 16);
                        LDSM4(bh[np][0], bh[np][1], bh[np][2], bh[np][3], baseBh + off);
                        LDSM4(bl[np][0], bl[np][1], bl[np][2], bl[np][3], baseBl + off);
                    }
#pragma unroll
                    for (int mt = 0; mt < 2; mt++)
#pragma unroll
                        for (int nt = 0; nt < 8; nt++) {
                            MMA_BF16(accO[mt][nt], a[mt],
                                     bh[nt >> 1][(nt & 1) * 2], bh[nt >> 1][(nt & 1) * 2 + 1]);
                            MMA_BF16(accO[mt][nt], a[mt],
                                     bl[nt >> 1][(nt & 1) * 2], bl[nt >> 1][(nt & 1) * 2 + 1]);
                        }
                }
            }
        }

        // ======== GEMM2 ========
        for (int kc64 = 0; kc64 < 2; kc64++) {
            __syncthreads();                        // prior sZ/sO reads done
            if (wn == kc64) {
                // repack relu(accO + bias) -> sO rows (bf16, SW128)
#pragma unroll
                for (int nt = 0; nt < 8; nt++) {
                    int colb = wn * 64 + nt * 8 + 2 * (lane & 3);
                    float2 bb = *(const float2*)&gb[l * CC + colb];
                    int kloc = nt * 8 + 2 * (lane & 3);
#pragma unroll
                    for (int mt = 0; mt < 2; mt++) {
                        int r = wm * 32 + mt * 16 + (lane >> 2);
                        uint32_t p0 = pk_bf16(fmaxf(accO[mt][nt][0] + bb.x, 0.f),
                                              fmaxf(accO[mt][nt][1] + bb.y, 0.f));
                        uint32_t p1 = pk_bf16(fmaxf(accO[mt][nt][2] + bb.x, 0.f),
                                              fmaxf(accO[mt][nt][3] + bb.y, 0.f));
                        *(uint32_t*)(sZ + SWZ128((uint32_t)(r * 128 + kloc * 2))) = p0;
                        *(uint32_t*)(sZ + SWZ128((uint32_t)((r + 8) * 128 + kloc * 2))) = p1;
                    }
                }
            }
            for (int kc32 = 0; kc32 < 2; kc32++) {
                __syncthreads();
                int chunk = kc64 * 2 + kc32;
                const uint4* srcH = (const uint4*)(g_Wh + (size_t)((1 * 4 + l) * 4 + chunk) * 4096);
                const uint4* srcL = (const uint4*)(g_Wl + (size_t)((1 * 4 + l) * 4 + chunk) * 4096);
#pragma unroll
                for (int it = 0; it < 2; it++) {
                    int idx = it * 256 + tid;
                    int n = idx >> 2, q = idx & 3;
                    *(uint4*)(sBh + n * 80 + q * 16) = srcH[idx];
                    *(uint4*)(sBl + n * 80 + q * 16) = srcL[idx];
                }
                __syncthreads();
#pragma unroll
                for (int ks = 0; ks < 2; ks++) {
                    int kin = kc32 * 32 + ks * 16;
                    uint32_t a[2][4];
#pragma unroll
                    for (int mt = 0; mt < 2; mt++) {
                        int r = wm * 32 + mt * 16 + (lane & 15);
                        uint32_t ad = baseZ + SWZ128((uint32_t)(r * 128 + kin * 2 + (lane >> 4) * 16));
                        LDSM4(a[mt][0], a[mt][1], a[mt][2], a[mt][3], ad);
                    }
                    uint32_t bh[4][4], bl[4][4];
#pragma unroll
                    for (int np = 0; np < 4; np++) {
                        int r = wn * 64 + np * 16 + (lane & 7) + ((lane >> 4) << 3);
                        uint32_t off = (uint32_t)(r * 80 + ks * 32 + ((lane >> 3) & 1) * 16);
                        LDSM4(bh[np][0], bh[np][1], bh[np][2], bh[np][3], baseBh + off);
                        LDSM4(bl[np][0], bl[np][1], bl[np][2], bl[np][3], baseBl + off);
                    }
#pragma unroll
                    for (int mt = 0; mt < 2; mt++)
#pragma unroll
                        for (int nt = 0; nt < 8; nt++) {
                            MMA_BF16(accF[mt][nt], a[mt],
                                     bh[nt >> 1][(nt & 1) * 2], bh[nt >> 1][(nt & 1) * 2 + 1]);
                            MMA_BF16(accF[mt][nt], a[mt],
                                     bl[nt >> 1][(nt & 1) * 2], bl[nt >> 1][(nt & 1) * 2 + 1]);
                        }
                }
            }
        }
    }

    // ======== epilogue: g_matrix partials + row norms + bf16 xn ========
    __syncthreads();
    if (tid < 128) { sgm[tid] = 0.f; sns[tid] = 0.f; }
    __syncthreads();
#pragma unroll
    for (int nt = 0; nt < 8; nt++) {
        float se = 0.f, so = 0.f;
#pragma unroll
        for (int mt = 0; mt < 2; mt++) {
            int r = wm * 32 + mt * 16 + (lane >> 2);
            if (row0 + r < NN)     { se += accF[mt][nt][0]; so += accF[mt][nt][1]; }
            if (row0 + r + 8 < NN) { se += accF[mt][nt][2]; so += accF[mt][nt][3]; }
        }
        int col = wn * 64 + nt * 8 + 2 * (lane & 3);
        atomicAdd(&sgm[col], se);
        atomicAdd(&sgm[col + 1], so);
    }
#pragma unroll
    for (int mt = 0; mt < 2; mt++) {
        float s0 = 0.f, s1 = 0.f;
#pragma unroll
        for (int nt = 0; nt < 8; nt++) {
            s0 += accF[mt][nt][0] * accF[mt][nt][0] + accF[mt][nt][1] * accF[mt][nt][1];
            s1 += accF[mt][nt][2] * accF[mt][nt][2] + accF[mt][nt][3] * accF[mt][nt][3];
        }
        s0 += __shfl_xor_sync(0xffffffffu, s0, 1);
        s0 += __shfl_xor_sync(0xffffffffu, s0, 2);
        s1 += __shfl_xor_sync(0xffffffffu, s1, 1);
        s1 += __shfl_xor_sync(0xffffffffu, s1, 2);
        if ((lane & 3) == 0) {
            int r = wm * 32 + mt * 16 + (lane >> 2);
            atomicAdd(&sns[r], s0);
            atomicAdd(&sns[r + 8], s1);
        }
    }
    __syncthreads();
    if (tid < 32)
        ((float4*)(g_gmp + (size_t)(g * NBLK + blockIdx.x) * CC))[tid] =
            ((const float4*)sgm)[tid];
#pragma unroll
    for (int mt = 0; mt < 2; mt++) {
        int r = wm * 32 + mt * 16 + (lane >> 2);
        float inv0 = 1.0f / fmaxf(sqrtf(sns[r]), 1e-12f);
        float inv1 = 1.0f / fmaxf(sqrtf(sns[r + 8]), 1e-12f);
        bool v0 = (row0 + r < NN), v1 = (row0 + r + 8 < NN);
#pragma unroll
        for (int nt = 0; nt < 8; nt++) {
            int col = wn * 64 + nt * 8 + 2 * (lane & 3);
            if (v0)
                *(uint32_t*)(g_xnb + ((size_t)g * NROWP + row0 + r) * CC + col) =
                    pk_bf16(accF[mt][nt][0] * inv0, accF[mt][nt][1] * inv0);
            if (v1)
                *(uint32_t*)(g_xnb + ((size_t)g * NROWP + row0 + r + 8) * CC + col) =
                    pk_bf16(accF[mt][nt][2] * inv1, accF[mt][nt][3] * inv1);
        }
    }
}

// ---------------- sim: bf16 mma, diag pairs folded for balance ----------------
__global__ void __launch_bounds__(256, 2) k_sim() {
    __shared__ __nv_bfloat16 sA[2][128 * 64];  // two SW128 K=64 chunks (32KB)
    __shared__ __nv_bfloat16 sB[128 * 40];     // K=32 chunk, rows padded to 80B
    __shared__ float s_bnd[22];
    __shared__ unsigned s_part[8];

    int p = blockIdx.y;
    int i1 = cP1[p], i2 = cP2[p];
    int bx = blockIdx.x;
    bool diag = (i1 == i2);
    int rows[2];
    int nrows = 1;
    rows[0] = bx;
    if (diag) {
        if (bx >= 24) return;
        rows[1] = 46 - bx;
        nrows = (bx == 23) ? 1 : 2;
    }

    int tid = threadIdx.x;
    int lane = tid & 31, wid = tid >> 5;
    int wm = wid & 3, wn = wid >> 2;
    if (tid < 22) s_bnd[tid] = c_bnd[tid];

    const __nv_bfloat16* A = g_xnb + (size_t)i1 * NROWP * CC;
    const __nv_bfloat16* B = g_xnb + (size_t)i2 * NROWP * CC;
    uint32_t baseA = smem_u32(sA), baseB = smem_u32(sB);

    unsigned total = 0;
    for (int ri = 0; ri < nrows; ri++) {
        int rb = rows[ri];
        int row0 = rb * 128;
        if (ri) __syncthreads();               // prior row's mma reads of sA done
#pragma unroll
        for (int it = 0; it < 8; it++) {
            int idx = it * 256 + tid;
            int kc = idx >> 10, rem = idx & 1023;
            int r = rem >> 3, q = rem & 7;
            uint32_t sw = (uint32_t)(kc * 16384) + SWZ128((uint32_t)(r * 128 + q * 16));
            *(uint4*)((uint8_t*)sA + sw) =
                *(const uint4*)(A + (size_t)(row0 + r) * CC + kc * 64 + q * 8);
        }
        int byStart = diag ? rb : 0;
        for (int by = byStart; by < 47; by++) {
            unsigned wgt = (diag && by > rb) ? 2u : 1u;
            int col0 = by * 128;
            float acc[2][8][4];
#pragma unroll
            for (int mt = 0; mt < 2; mt++)
#pragma unroll
                for (int nt = 0; nt < 8; nt++) {
                    acc[mt][nt][0] = 0.f; acc[mt][nt][1] = 0.f;
                    acc[mt][nt][2] = 0.f; acc[mt][nt][3] = 0.f;
                }
#pragma unroll
            for (int bc = 0; bc < 4; bc++) {
                __syncthreads();
#pragma unroll
                for (int it = 0; it < 2; it++) {
                    int idx = it * 256 + tid;
                    int r = idx >> 2, q = idx & 3;
                    *(uint4*)((uint8_t*)sB + r * 80 + q * 16) =
                        *(const uint4*)(B + (size_t)(col0 + r) * CC + bc * 32 + q * 8);
                }
                __syncthreads();
#pragma unroll
                for (int ks = 0; ks < 2; ks++) {
                    int kg = bc * 32 + ks * 16;
                    int akc = kg >> 6, akb = (kg & 63) * 2;
                    uint32_t a[2][4];
#pragma unroll
                    for (int mt = 0; mt < 2; mt++) {
                        int r = wm * 32 + mt * 16 + (lane & 15);
                        uint32_t ad = baseA + akc * 16384 +
                            SWZ128((uint32_t)(r * 128 + akb + (lane >> 4) * 16));
                        LDSM4(a[mt][0], a[mt][1], a[mt][2], a[mt][3], ad);
                    }
                    uint32_t b[4][4];
#pragma unroll
                    for (int np = 0; np < 4; np++) {
                        int r = wn * 64 + np * 16 + (lane & 7) + ((lane >> 4) << 3);
                        uint32_t bd = baseB + (uint32_t)(r * 80 + ks * 32 + ((lane >> 3) & 1) * 16);
                        LDSM4(b[np][0], b[np][1], b[np][2], b[np][3], bd);
                    }
#pragma unroll
                    for (int mt = 0; mt < 2; mt++)
#pragma unroll
                        for (int nt = 0; nt < 8; nt++)
                            MMA_BF16(acc[mt][nt], a[mt],
                                     b[nt >> 1][(nt & 1) * 2], b[nt >> 1][(nt & 1) * 2 + 1]);
                }
            }
            // bin accumulators (exact w.r.t. fp32 s; see R8 margin proof)
            int sum = 0;
#pragma unroll
            for (int mt = 0; mt < 2; mt++)
#pragma unroll
                for (int nt = 0; nt < 8; nt++)
#pragma unroll
                    for (int v = 0; v < 4; v++) {
                        float s = acc[mt][nt][v];
                        float t;
                        asm("tanh.approx.f32 %0, %1;" : "=f"(t) : "f"(s));
                        int idx = __float2int_rd(fmaf(t, 10.5f, 10.43f));
                        sum += idx + ((s >= s_bnd[idx + 1]) ? 1 : 0);
                    }
            total += wgt * (unsigned)sum;
        }
    }
#pragma unroll
    for (int o = 16; o; o >>= 1) total += __shfl_xor_sync(0xffffffffu, total, o);
    if (lane == 0) s_part[wid] = total;
    __syncthreads();
    if (tid == 0) {
        unsigned tot = 0;
#pragma unroll
        for (int i = 0; i < 8; i++) tot += s_part[i];
        atomicAdd(&g_cnt[p], tot);
    }
}

// ---------------- finalize: g_matrix reduce + sim values ----------------
__global__ void k_final(float* __restrict__ out) {
    int t = threadIdx.x;
    if (t < NGG * CC) {
        int g = t / CC, c = t - g * CC;
        float s = 0.f;
        for (int b = 0; b < NBLK; b++)
            s += g_gmp[(size_t)(g * NBLK + b) * CC + c];
        out[t] = s / (float)NN;
    }
    if (t < NPAIR) {
        double cnt = (double)g_cnt[t] - 10.0 * 192256.0;
        double v = -1.0 + 0.1 * cnt / ((double)NN * (double)NN);
        out[NGG * CC + cP1[t] * NGG + cP2[t]] = (float)v;
        out[NGG * CC + cP2[t] * NGG + cP1[t]] = (float)v;
    }
}

// ---------------- launch ----------------
extern "C" void kernel_launch(void* const* d_in, const int* in_sizes, int n_in,
                              void* d_out, int out_size) {
    const float* x   = (const float*)d_in[0];
    const int* ei    = (const int*)d_in[1];
    const float* ea  = (const float*)d_in[2];
    const float* gW  = (const float*)d_in[3];
    const float* gb  = (const float*)d_in[4];
    const float* Wsm = (const float*)d_in[5];
    float* out = (float*)d_out;

    k_setup<<<(NGG * NN * 4 + 255) / 256, 256>>>(gW, Wsm);
    k_deg<<<(NGG * EE + 255) / 256, 256>>>(ei, ea);
    k_scan<<<NGG, 256>>>();
    k_fill<<<(NGG * EE + 255) / 256, 256>>>(ei, ea);
    k_gather<<<(NGG * NN + 7) / 8, 256>>>(x);
    k_fused<<<dim3(NBLK, NGG), 256>>>(gb);
    k_sim<<<dim3(47, NPAIR), 256>>>();
    k_final<<<1, 768>>>(out);
}